// round 16
// baseline (speedup 1.0000x reference)
#include <cuda_runtime.h>
#include <cstdint>

// ============================================================================
// CINLayer: out_mat[b,c,d] = sum_{i,j} kernel[c,i,j] * x[b,i,d] * y[b,j,d]
//           final[b,c]     = sum_d out_mat[b,c,d]
// GEMM mapping: Z[(b,d),(i,j)] = x[b,i,d]*y[b,j,d] (fp16, built in regs)
//               out = Z(131072 x 1024) @ kernel^T(1024 x 64)
// via mma.sync.m16n8k16.f32.f16.f16.f32.
// R16: 2 CTAs/SM discriminating experiment. Each CTA owns ONE c-half
//      (KP = 64KB -> SMEM 99.3KB -> true 2-CTA residency, 4 warps/SMSP).
//      Independent CTA barriers let one CTA's tensor stream run while the
//      other stages/epilogues; tests whether the ~45% tensor ceiling is
//      whole-CTA serialization (H-B) or a hard legacy-HMMA rate (H-A).
// ============================================================================

#define B_DIM 4096
#define H_DIM 32
#define C_DIM 64
#define D_DIM 32

namespace cin {

constexpr int THREADS   = 256;
constexpr int GRID      = 296;                          // 2 CTAs per pass slot
constexpr int PASS_ROWS = 128;                          // 4 b's x 32 d per pass
constexpr int N_PASSES  = (B_DIM * D_DIM) / PASS_ROWS;  // 1024
constexpr int KSTEPS    = 64;                           // K=1024 / k16

// SMEM (bytes)
constexpr int SM_KP   = 0;                      // packed fp16 kernel HALF: 64KB
constexpr int KP_SZ   = KSTEPS * 2 * 32 * 16;   // 65536
constexpr int XY_STRIDE = 132;                  // stage row stride (words)
constexpr int XS_SZ   = 32 * XY_STRIDE * 4;     // 16896
constexpr int STG_SZ  = 2 * XS_SZ;              // x + y = 33792
constexpr int SM_STG  = SM_KP + KP_SZ;          // single stage buffer
// epilogue buffer aliases the stage buffer: [128 rows][34] f32 = 17408
constexpr int BUF_STRIDE = 34;                  // even -> sts64f 8B aligned
static_assert(PASS_ROWS * BUF_STRIDE * 4 <= STG_SZ, "BUF must fit stage buffer");
constexpr unsigned SMEM_TOTAL = (unsigned)(SM_STG + STG_SZ);   // 99328

__device__ __forceinline__ uint32_t smem_u32(const void* p) {
    uint32_t a;
    asm("{ .reg .u64 t; cvta.to.shared.u64 t, %1; cvt.u32.u64 %0, t; }"
        : "=r"(a) : "l"(p));
    return a;
}
// pack two f32 -> f16x2 (hi = first arg -> high half)
__device__ __forceinline__ uint32_t cvt2(float hi, float lo) {
    uint32_t r;
    asm("cvt.rn.f16x2.f32 %0, %1, %2;" : "=r"(r) : "f"(hi), "f"(lo));
    return r;
}
// packed fp16 multiply (fixed-latency fma-class: rt2, lat4)
__device__ __forceinline__ uint32_t hmul2(uint32_t a, uint32_t b) {
    uint32_t r;
    asm("mul.rn.f16x2 %0, %1, %2;" : "=r"(r) : "r"(a), "r"(b));
    return r;
}
__device__ __forceinline__ void sts32(uint32_t a, uint32_t v) {
    asm volatile("st.shared.b32 [%0], %1;" :: "r"(a), "r"(v) : "memory");
}
__device__ __forceinline__ void sts64f(uint32_t a, float v0, float v1) {
    asm volatile("st.shared.v2.f32 [%0], {%1,%2};"
                 :: "r"(a), "f"(v0), "f"(v1) : "memory");
}
__device__ __forceinline__ float ldsf(uint32_t a) {
    float v;
    asm volatile("ld.shared.f32 %0, [%1];" : "=f"(v) : "r"(a));
    return v;
}
__device__ __forceinline__ void lds128(uint32_t* r, uint32_t a) {
    asm volatile("ld.shared.v4.b32 {%0,%1,%2,%3}, [%4];"
                 : "=r"(r[0]), "=r"(r[1]), "=r"(r[2]), "=r"(r[3]) : "r"(a));
}
__device__ __forceinline__ void cp_async16(uint32_t smem_a, const float* g) {
    asm volatile("cp.async.ca.shared.global [%0], [%1], 16;"
                 :: "r"(smem_a), "l"(g) : "memory");
}
__device__ __forceinline__ void cp_commit() {
    asm volatile("cp.async.commit_group;" ::: "memory");
}
__device__ __forceinline__ void cp_wait0() {
    asm volatile("cp.async.wait_group 0;" ::: "memory");
}
__device__ __forceinline__ void mma16816(float* c, uint32_t a0, uint32_t a1,
                                         uint32_t a2, uint32_t a3,
                                         uint32_t b0, uint32_t b1) {
    asm volatile(
        "mma.sync.aligned.m16n8k16.row.col.f32.f16.f16.f32 "
        "{%0,%1,%2,%3}, {%4,%5,%6,%7}, {%8,%9}, {%0,%1,%2,%3};"
        : "+f"(c[0]), "+f"(c[1]), "+f"(c[2]), "+f"(c[3])
        : "r"(a0), "r"(a1), "r"(a2), "r"(a3), "r"(b0), "r"(b1));
}

// issue the 8 cp.asyncs staging one pass's x & y into the stage buffer
__device__ __forceinline__ void issue_stage(uint32_t stg, const float* Xp,
                                            const float* Yp, int tid) {
#pragma unroll
    for (int it = 0; it < 4; it++) {
        const int idx = tid + it * 256;        // float4 idx, 0..1023
        const int b_l = idx >> 8;
        const int i   = (idx >> 3) & 31;
        const int d4  = (idx & 7) * 4;
        const uint32_t off = (uint32_t)(i * XY_STRIDE + b_l * 32 + d4) * 4;
        cp_async16(stg + off,         Xp + idx * 4);
        cp_async16(stg + XS_SZ + off, Yp + idx * 4);
    }
}

__global__ void __launch_bounds__(THREADS, 2)
cin_kernel(const float* __restrict__ X, const float* __restrict__ Y,
           const float* __restrict__ Kmat, float* __restrict__ out_mat,
           float* __restrict__ out_fin) {
    extern __shared__ char smem[];
    const uint32_t sb = smem_u32(smem);
    const int bid  = blockIdx.x;
    const int ch   = bid & 1;       // this CTA's c-half (c = ch*32 .. +31)
    const int p0   = bid >> 1;      // first pass index
    const int tid  = threadIdx.x;
    const int w    = tid >> 5;
    const int lane = tid & 31;
    const int g    = lane >> 2;     // row group within fragment
    const int t3   = lane & 3;      // col group within fragment
    const int r1   = w * 16 + g;    // warp = 16 rows x 32 cols (c-half)
    const int r2   = r1 + 8;

    const uint32_t stg = sb + SM_STG;
    const uint32_t xs  = stg;
    const uint32_t ys  = stg + XS_SZ;
    // per-warp base of the B fragment stream (2 chunks per step = 1024 B)
    const uint32_t kpb = sb + SM_KP + lane * 16;

    // ---------------- prologue: stage first pass via cp.async ---------------
    issue_stage(stg, X + p0 * 4096, Y + p0 * 4096, tid);
    cp_commit();

    // ---------------- stage this CTA's kernel c-half into packed fp16 -------
    // local layout: addr = ((s*2 + q')*32 + l0)*16 + w_in*4, q' = local chunk
    //   local frag f (=tt_loc 0..3) covers c_loc = f*8 + (l>>2)
    {
        const float4* K4 = reinterpret_cast<const float4*>(Kmat);
        for (int it = 0; it < 32; it++) {
            const int fl    = tid + it * 256;       // local float4 idx 0..8191
            const int c_loc = fl >> 8;              // 0..31
            const int rr    = fl & 255;             // float4 within row
            const int idx   = ((ch * 32 + c_loc) << 8) + rr;
            const float4 v  = K4[idx];
            const int flat  = idx * 4;
            const int s     = (flat & 1023) >> 4;
            const int kk    = flat & 15;
            const int ttl   = c_loc >> 3;           // local tt 0..3
            const int qp    = ttl >> 1;             // local chunk 0..1
            const int hi    = kk >> 3;
            const int w_in  = (ttl & 1) * 2 + hi;
            const int l0    = (c_loc & 7) * 4 + ((kk & 7) >> 1);
            const uint32_t addr =
                sb + SM_KP + (((s * 2 + qp) * 32 + l0) << 4) + (w_in << 2);
            sts32(addr,      cvt2(v.y, v.x));
            sts32(addr + 16, cvt2(v.w, v.z));
        }
    }

    // ---------------- persistent loop over passes ---------------------------
    for (int p = p0; p < N_PASSES; p += 148) {
        cp_wait0();          // stage data arrived
        __syncthreads();     // visible to all warps; KP pack / prev epi done

        // pre-rounded y fragments: yh2[r][u] = f16x2(y[j0+1] hi, y[j0] lo),
        // u = 2*h + v, j0 = 2*t3 + v*8 + h*16
        uint32_t yh2[2][4];
#pragma unroll
        for (int u = 0; u < 4; u++) {
            const int j0 = 2 * t3 + (u & 1) * 8 + (u >> 1) * 16;
            const uint32_t b0 = ys + (uint32_t)(j0 * XY_STRIDE) * 4;
            const uint32_t b1 = ys + (uint32_t)((j0 + 1) * XY_STRIDE) * 4;
            yh2[0][u] = cvt2(ldsf(b1 + (uint32_t)r1 * 4),
                             ldsf(b0 + (uint32_t)r1 * 4));
            yh2[1][u] = cvt2(ldsf(b1 + (uint32_t)r2 * 4),
                             ldsf(b0 + (uint32_t)r2 * 4));
        }

        float acc[16];
#pragma unroll
        for (int z = 0; z < 16; z++) acc[z] = 0.0f;

        // ---------------- mainloop: i = 0..31, two k16-steps per i ----------
        // per step/warp: 2 LDS.128 (B) + 4 HMUL2 + 4 HMMA. No converts.
#pragma unroll 4
        for (int i = 0; i < 32; i++) {
            const uint32_t xb = xs + (uint32_t)(i * XY_STRIDE) * 4;
            const float xf0 = ldsf(xb + (uint32_t)r1 * 4);
            const float xf1 = ldsf(xb + (uint32_t)r2 * 4);
            const uint32_t xh0 = cvt2(xf0, xf0);
            const uint32_t xh1 = cvt2(xf1, xf1);
#pragma unroll
            for (int h = 0; h < 2; h++) {
                const int s = i * 2 + h;
                uint32_t bb[8];
                const uint32_t bbase = kpb + (uint32_t)s * 1024;
                lds128(bb + 0, bbase);
                lds128(bb + 4, bbase + 512);
                const uint32_t a0 = hmul2(xh0, yh2[0][2 * h + 0]);
                const uint32_t a1 = hmul2(xh1, yh2[1][2 * h + 0]);
                const uint32_t a2 = hmul2(xh0, yh2[0][2 * h + 1]);
                const uint32_t a3 = hmul2(xh1, yh2[1][2 * h + 1]);
#pragma unroll
                for (int f = 0; f < 4; f++) {
                    const int bi = (f >> 1) * 4 + (f & 1) * 2;
                    mma16816(acc + f * 4, a0, a1, a2, a3, bb[bi], bb[bi + 1]);
                }
            }
        }

        __syncthreads();   // all warps done reading xs/ys; BUF aliases stg

        // ---------------- epilogue: frags -> padded SMEM (BUF = stg) --------
#pragma unroll
        for (int f = 0; f < 4; f++) {
            const int c_lo = f * 8 + 2 * t3;    // even, 0..30 (c-half local)
            const float* a = acc + f * 4;
            sts64f(stg + (uint32_t)(r1 * BUF_STRIDE + c_lo) * 4, a[0], a[1]);
            sts64f(stg + (uint32_t)(r2 * BUF_STRIDE + c_lo) * 4, a[2], a[3]);
        }
        __syncthreads();

        // ------- epi: thread = (b_l, c_loc, d-half), 16 d's each ------------
        {
            const int b_l   = tid >> 6;             // 0..3
            const int c_loc = (tid >> 1) & 31;      // 0..31
            const int dh    = tid & 1;              // which 16-d half
            const int b     = p * 4 + b_l;
            const int cg    = ch * 32 + c_loc;
            float* dst = out_mat + ((size_t)b * C_DIM + cg) * D_DIM + dh * 16;
            const uint32_t rbase =
                stg + (uint32_t)((b_l * 32 + dh * 16) * BUF_STRIDE + c_loc) * 4;
            float srow = 0.0f;
#pragma unroll
            for (int g4 = 0; g4 < 4; g4++) {
                const uint32_t a = rbase + (uint32_t)(g4 * 4 * BUF_STRIDE) * 4;
                float v0 = ldsf(a);
                float v1 = ldsf(a + BUF_STRIDE * 4);
                float v2 = ldsf(a + 2 * BUF_STRIDE * 4);
                float v3 = ldsf(a + 3 * BUF_STRIDE * 4);
                *reinterpret_cast<float4*>(dst + g4 * 4) =
                    make_float4(v0, v1, v2, v3);
                srow += (v0 + v1) + (v2 + v3);
            }
            srow += __shfl_xor_sync(0xffffffffu, srow, 1);
            if (dh == 0) out_fin[b * C_DIM + cg] = srow;
        }
        __syncthreads();   // epi reads done before next stage overwrites

        // ---------------- stage next pass ------------------------------------
        const int pn = p + 148;
        if (pn < N_PASSES) {
            issue_stage(stg, X + pn * 4096, Y + pn * 4096, tid);
            cp_commit();
        }
    }
}

}  // namespace cin

extern "C" void kernel_launch(void* const* d_in, const int* in_sizes, int n_in,
                              void* d_out, int out_size) {
    // Expected order: x [B,H1,D], y [B,H2,D], kernel [C,H1,H2].
    // Defensive remap: kernel is uniquely the 65536-element input.
    const float* x = (const float*)d_in[0];
    const float* y = (const float*)d_in[1];
    const float* k = (const float*)d_in[2];
    if (n_in == 3) {
        if (in_sizes[0] == C_DIM * H_DIM * H_DIM) {
            k = (const float*)d_in[0]; x = (const float*)d_in[1]; y = (const float*)d_in[2];
        } else if (in_sizes[1] == C_DIM * H_DIM * H_DIM) {
            x = (const float*)d_in[0]; k = (const float*)d_in[1]; y = (const float*)d_in[2];
        }
    }
    float* out_mat = (float*)d_out;
    float* out_fin = out_mat + (size_t)B_DIM * C_DIM * D_DIM;

    cudaFuncSetAttribute(cin::cin_kernel,
                         cudaFuncAttributeMaxDynamicSharedMemorySize,
                         cin::SMEM_TOTAL);
    cin::cin_kernel<<<cin::GRID, cin::THREADS, cin::SMEM_TOTAL>>>(
        x, y, k, out_mat, out_fin);
}